// round 2
// baseline (speedup 1.0000x reference)
#include <cuda_runtime.h>
#include <cstdint>

#define NUM_USER   4096
#define NUM_ITEM   16384
#define NUM_HIDDEN 64
#define BATCH      1024
#define SETLEN     50
#define NJ         (BATCH * SETLEN)              // 51200 scatter updates

#define PLANE      ((size_t)NUM_USER * NUM_ITEM) // 67,108,864 cells
#define GROUPS     (PLANE / 32)                  // 2,097,152 groups of 32 cells

#define HASH_BITS  18
#define HASH_SIZE  (1u << HASH_BITS)             // 262144 slots, load ~0.2
#define HASH_MASK  (HASH_SIZE - 1u)
#define IDX_MASK   0x1FFFFull                    // linear idx fits in 17 bits

// ---------------------------------------------------------------------------
// Persistent device state. INVARIANT: at the start of every kernel_launch
// (first call AND every graph replay), all of this is zero. The fused writer
// kernel restores it as it consumes entries, so no clear pass is needed.
// ---------------------------------------------------------------------------
__device__ unsigned long long g_hash[HASH_SIZE]; // (cell+1)<<17 | linear j
__device__ unsigned int       g_nnz;             // unique-cell count
__device__ int                g_head[GROUPS];    // per-group list head, j+1; 0=empty
// Per-update node storage (indexed by j, no allocator/counter needed):
__device__ int                g_next [NJ];       // next j+1 in group list; 0=tail
__device__ unsigned int       g_cell [NJ];
__device__ unsigned int       g_slot [NJ];       // hash slot owned by this winner
__device__ float              g_pred [NJ];
__device__ float              g_label[NJ];

__device__ __forceinline__ unsigned int hash_cell(unsigned int c) {
    c *= 2654435761u;                            // Knuth multiplicative
    return (c >> 8) & HASH_MASK;
}

// ---------------------------------------------------------------------------
// 1) Insert all (cell, j) pairs. Duplicate cells: atomicMax keeps the LARGEST
//    j == last-write-wins in (b,l) row-major order (XLA scatter semantics).
//    First CAS into an empty slot counts one unique cell -> sum(mask).
// ---------------------------------------------------------------------------
__global__ void insert_kernel(const int* __restrict__ idx_user,
                              const int* __restrict__ item_sets) {
    int j = blockIdx.x * blockDim.x + threadIdx.x;
    if (j >= NJ) return;
    int b = j / SETLEN;
    unsigned int u    = (unsigned int)idx_user[b];
    unsigned int it   = (unsigned int)item_sets[j];
    unsigned int cell = u * NUM_ITEM + it;

    unsigned long long keyhi = ((unsigned long long)(cell + 1u)) << 17;
    unsigned long long val   = keyhi | (unsigned long long)(unsigned int)j;

    unsigned int h = hash_cell(cell);
    while (true) {
        unsigned long long cur = g_hash[h];
        if (cur == 0ull) {
            unsigned long long old = atomicCAS(&g_hash[h], 0ull, val);
            if (old == 0ull) {                   // claimed empty: first occurrence
                atomicAdd(&g_nnz, 1u);
                break;
            }
            cur = old;
        }
        if ((cur & ~IDX_MASK) == keyhi) {        // same key: keep max j
            atomicMax(&g_hash[h], val);
            break;
        }
        h = (h + 1u) & HASH_MASK;                // different key: linear probe
    }
}

// ---------------------------------------------------------------------------
// 2) Winners compute their dot product and enqueue a node on their 32-cell
//    group's linked list (head stores j+1; next stores old head; 0 = empty,
//    matching the static-zero pristine state).
// ---------------------------------------------------------------------------
__global__ void prepare_kernel(const int*   __restrict__ idx_user,
                               const int*   __restrict__ item_sets,
                               const float* __restrict__ ratings,
                               const float* __restrict__ embed_user,
                               const float* __restrict__ embed_item) {
    int j = blockIdx.x * blockDim.x + threadIdx.x;
    if (j >= NJ) return;
    int b = j / SETLEN;
    unsigned int u    = (unsigned int)idx_user[b];
    unsigned int it   = (unsigned int)item_sets[j];
    unsigned int cell = u * NUM_ITEM + it;

    unsigned long long keyhi = ((unsigned long long)(cell + 1u)) << 17;
    unsigned int h = hash_cell(cell);
    unsigned long long cur;
    while (((cur = g_hash[h]) & ~IDX_MASK) != keyhi) h = (h + 1u) & HASH_MASK;

    if ((unsigned int)(cur & IDX_MASK) != (unsigned int)j) return;  // not winner

    // 64-dim dot, float4-vectorized (rows are 256B-aligned)
    const float4* ur = (const float4*)(embed_user + (size_t)u  * NUM_HIDDEN);
    const float4* ir = (const float4*)(embed_item + (size_t)it * NUM_HIDDEN);
    float acc = 0.0f;
#pragma unroll
    for (int k = 0; k < NUM_HIDDEN / 4; k++) {
        float4 a = ur[k];
        float4 c = ir[k];
        acc = fmaf(a.x, c.x, acc);
        acc = fmaf(a.y, c.y, acc);
        acc = fmaf(a.z, c.z, acc);
        acc = fmaf(a.w, c.w, acc);
    }

    g_pred [j] = acc;
    g_label[j] = ratings[j];
    g_cell [j] = cell;
    g_slot [j] = h;
    int old = atomicExch(&g_head[cell >> 5], j + 1);
    g_next[j] = old;                             // 0 terminates (pristine state)
}

// ---------------------------------------------------------------------------
// 3) Fused zero-fill + scatter. One thread per 32-cell group writes 128B of
//    each plane. Untouched group (head==0, ~99.3%): pure zero stores. Touched
//    group: zeros, then overwrite listed cells with pred/label; also restores
//    g_head, g_hash slots (each owned by exactly one walker) to zero.
//    Thread 0 emits sparsity and resets g_nnz.
// ---------------------------------------------------------------------------
__global__ void write_kernel(float* __restrict__ out) {
    size_t g = (size_t)blockIdx.x * blockDim.x + threadIdx.x;
    if (g >= GROUPS) return;

    if (g == 0) {
        double total = (double)PLANE;
        out[2 * PLANE] = (float)(total / (double)g_nnz);
        g_nnz = 0u;                              // restore pristine state
    }

    int head = g_head[g];
    float4  z  = make_float4(0.f, 0.f, 0.f, 0.f);
    float4* p0 = (float4*)(out + g * 32);
    float4* p1 = (float4*)(out + PLANE + g * 32);
#pragma unroll
    for (int k = 0; k < 8; k++) p0[k] = z;
#pragma unroll
    for (int k = 0; k < 8; k++) p1[k] = z;

    if (head != 0) {                             // rare: patch in values
        int cur = head;
        while (cur != 0) {
            int j = cur - 1;
            unsigned int cell = g_cell[j];
            out[cell]         = g_pred[j];
            out[PLANE + cell] = g_label[j];
            g_hash[g_slot[j]] = 0ull;            // restore pristine state
            cur = g_next[j];
        }
        g_head[g] = 0;                           // restore pristine state
    }
}

// ---------------------------------------------------------------------------
extern "C" void kernel_launch(void* const* d_in, const int* in_sizes, int n_in,
                              void* d_out, int out_size) {
    const int*   idx_user   = (const int*)  d_in[0];
    const int*   item_sets  = (const int*)  d_in[1];
    const float* rating     = (const float*)d_in[2];
    const float* embed_user = (const float*)d_in[3];
    const float* embed_item = (const float*)d_in[4];
    float* out = (float*)d_out;

    insert_kernel <<<(NJ + 255) / 256, 256>>>(idx_user, item_sets);
    prepare_kernel<<<(NJ + 255) / 256, 256>>>(idx_user, item_sets, rating,
                                              embed_user, embed_item);
    write_kernel  <<<(GROUPS + 255) / 256, 256>>>(out);
}

// round 4
// speedup vs baseline: 1.9645x; 1.9645x over previous
#include <cuda_runtime.h>
#include <cstdint>

#define NUM_USER   4096
#define NUM_ITEM   16384
#define NUM_HIDDEN 64
#define BATCH      1024
#define SETLEN     50
#define NJ         (BATCH * SETLEN)              // 51200 scatter updates

#define PLANE      ((size_t)NUM_USER * NUM_ITEM) // 67,108,864 cells
#define GROUPS     (PLANE / 32)                  // 2,097,152 groups of 32 cells
#define WBLOCK     256                           // writer block size
#define CELLS_PER_BLOCK (WBLOCK * 32)            // 8192 cells per writer block

#define HASH_BITS  18
#define HASH_SIZE  (1u << HASH_BITS)             // 262144 slots, load ~0.2
#define HASH_MASK  (HASH_SIZE - 1u)
#define IDX_MASK   0x1FFFFull                    // linear idx fits in 17 bits

// ---------------------------------------------------------------------------
// Persistent device state. INVARIANT: zero at the start of every launch /
// graph replay. The writer kernel restores it as it consumes entries.
// ---------------------------------------------------------------------------
__device__ unsigned long long g_hash[HASH_SIZE]; // (cell+1)<<17 | linear j
__device__ unsigned int       g_nnz;             // unique-cell count
__device__ int                g_head[GROUPS];    // per-group head, j+1; 0=empty
__device__ int                g_next [NJ];       // next j+1; 0 = tail
__device__ unsigned int       g_cell [NJ];
__device__ unsigned int       g_slot [NJ];       // hash slot owned by winner
__device__ float              g_pred [NJ];
__device__ float              g_label[NJ];

__device__ __forceinline__ unsigned int hash_cell(unsigned int c) {
    c *= 2654435761u;
    return (c >> 8) & HASH_MASK;
}

// ---------------------------------------------------------------------------
// 1) Insert (cell, j). Duplicates: atomicMax keeps max j == last-write-wins
//    in (b,l) row-major order (XLA scatter semantics). First CAS into an
//    empty slot counts one unique cell -> sum(mask).
// ---------------------------------------------------------------------------
__global__ void insert_kernel(const int* __restrict__ idx_user,
                              const int* __restrict__ item_sets) {
    int j = blockIdx.x * blockDim.x + threadIdx.x;
    if (j >= NJ) return;
    int b = j / SETLEN;
    unsigned int u    = (unsigned int)__ldg(idx_user + b);
    unsigned int it   = (unsigned int)__ldg(item_sets + j);
    unsigned int cell = u * NUM_ITEM + it;

    unsigned long long keyhi = ((unsigned long long)(cell + 1u)) << 17;
    unsigned long long val   = keyhi | (unsigned long long)(unsigned int)j;

    unsigned int h = hash_cell(cell);
    while (true) {
        unsigned long long cur = g_hash[h];
        if (cur == 0ull) {
            unsigned long long old = atomicCAS(&g_hash[h], 0ull, val);
            if (old == 0ull) {                   // first occurrence of cell
                atomicAdd(&g_nnz, 1u);
                break;
            }
            cur = old;
        }
        if ((cur & ~IDX_MASK) == keyhi) {        // same key: keep max j
            atomicMax(&g_hash[h], val);
            break;
        }
        h = (h + 1u) & HASH_MASK;
    }
}

// ---------------------------------------------------------------------------
// 2) Winners compute their dot product and enqueue on their group's list
//    (head stores j+1, next stores old head, 0 = empty = pristine state).
// ---------------------------------------------------------------------------
__global__ void prepare_kernel(const int*   __restrict__ idx_user,
                               const int*   __restrict__ item_sets,
                               const float* __restrict__ ratings,
                               const float* __restrict__ embed_user,
                               const float* __restrict__ embed_item) {
    int j = blockIdx.x * blockDim.x + threadIdx.x;
    if (j >= NJ) return;
    int b = j / SETLEN;
    unsigned int u    = (unsigned int)__ldg(idx_user + b);
    unsigned int it   = (unsigned int)__ldg(item_sets + j);
    unsigned int cell = u * NUM_ITEM + it;

    unsigned long long keyhi = ((unsigned long long)(cell + 1u)) << 17;
    unsigned int h = hash_cell(cell);
    unsigned long long cur;
    while (((cur = g_hash[h]) & ~IDX_MASK) != keyhi) h = (h + 1u) & HASH_MASK;

    if ((unsigned int)(cur & IDX_MASK) != (unsigned int)j) return;  // not winner

    const float4* ur = (const float4*)(embed_user + (size_t)u  * NUM_HIDDEN);
    const float4* ir = (const float4*)(embed_item + (size_t)it * NUM_HIDDEN);
    float acc = 0.0f;
#pragma unroll
    for (int k = 0; k < NUM_HIDDEN / 4; k++) {
        float4 a = ur[k];
        float4 c = ir[k];
        acc = fmaf(a.x, c.x, acc);
        acc = fmaf(a.y, c.y, acc);
        acc = fmaf(a.z, c.z, acc);
        acc = fmaf(a.w, c.w, acc);
    }

    g_pred [j] = acc;
    g_label[j] = ratings[j];
    g_cell [j] = cell;
    g_slot [j] = h;
    int old = atomicExch(&g_head[cell >> 5], j + 1);
    g_next[j] = old;                             // 0 terminates
}

// ---------------------------------------------------------------------------
// 3) Fused zero-fill + scatter, COALESCED. Block b owns cells
//    [b*8192, (b+1)*8192) in each plane. Phase 1: grid-coalesced float4
//    zero stores (each warp store = 512 contiguous bytes = 4 full lines).
//    __syncthreads() (CTA-scope fence semantics) orders phase-2 patches
//    after the zeros. Phase 2: thread t walks group (b*256+t)'s list,
//    patches cells, and restores g_head / g_hash / g_nnz to zero.
// ---------------------------------------------------------------------------
__global__ __launch_bounds__(WBLOCK)
void write_kernel(float* __restrict__ out) {
    const int b   = blockIdx.x;
    const int tid = threadIdx.x;
    const size_t base = (size_t)b * CELLS_PER_BLOCK;
    const size_t g    = (size_t)b * WBLOCK + tid;

    // Issue head load early; ~600cy latency hides under the zero stores.
    int head = g_head[g];

    if (b == 0 && tid == 0) {
        out[2 * PLANE] = (float)((double)PLANE / (double)g_nnz);
        g_nnz = 0u;
    }

    float4  z  = make_float4(0.f, 0.f, 0.f, 0.f);
    float4* p0 = (float4*)(out + base);          // 2048 float4s per block
    float4* p1 = (float4*)(out + PLANE + base);
#pragma unroll
    for (int k = 0; k < 8; k++) {                // coalesced: stride WBLOCK
        p0[k * WBLOCK + tid] = z;
        p1[k * WBLOCK + tid] = z;
    }

    __syncthreads();                             // order patches after zeros

    if (head != 0) {
        int cur = head;
        while (cur != 0) {
            int j = cur - 1;
            unsigned int cell = g_cell[j];
            out[cell]         = g_pred[j];
            out[PLANE + cell] = g_label[j];
            g_hash[g_slot[j]] = 0ull;            // restore pristine state
            cur = g_next[j];
        }
        g_head[g] = 0;                           // restore pristine state
    }
}

// ---------------------------------------------------------------------------
extern "C" void kernel_launch(void* const* d_in, const int* in_sizes, int n_in,
                              void* d_out, int out_size) {
    const int*   idx_user   = (const int*)  d_in[0];
    const int*   item_sets  = (const int*)  d_in[1];
    const float* rating     = (const float*)d_in[2];
    const float* embed_user = (const float*)d_in[3];
    const float* embed_item = (const float*)d_in[4];
    float* out = (float*)d_out;

    insert_kernel <<<(NJ + 127) / 128, 128>>>(idx_user, item_sets);
    prepare_kernel<<<(NJ + 127) / 128, 128>>>(idx_user, item_sets, rating,
                                              embed_user, embed_item);
    write_kernel  <<<GROUPS / WBLOCK, WBLOCK>>>(out);
}

// round 5
// speedup vs baseline: 2.0728x; 1.0551x over previous
#include <cuda_runtime.h>
#include <cstdint>

#define NUM_USER   4096
#define NUM_ITEM   16384
#define NUM_HIDDEN 64
#define BATCH      1024
#define SETLEN     50
#define NJ         (BATCH * SETLEN)              // 51200 scatter updates

#define PLANE      ((size_t)NUM_USER * NUM_ITEM) // 67,108,864 cells
#define WINNER_BIT 0x80000000u                   // cell < 2^26, bit31 free

#define HASH_BITS  18
#define HASH_SIZE  (1u << HASH_BITS)             // 262144 slots, load ~0.2
#define HASH_MASK  (HASH_SIZE - 1u)
#define IDX_MASK   0x1FFFFull                    // linear idx fits in 17 bits

// ---------------------------------------------------------------------------
// Device scratch (static: no allocation allowed). All of it is fully
// rewritten every launch (clear_kernel + prepare writes all NJ slots), so
// no cross-replay state leaks.
// ---------------------------------------------------------------------------
__device__ unsigned long long g_hash[HASH_SIZE]; // (cell+1)<<17 | linear j
__device__ unsigned int       g_nnz;
__device__ unsigned int       g_cell [NJ];       // cell|WINNER_BIT, or 0
__device__ float              g_pred [NJ];
__device__ float              g_label[NJ];

__device__ __forceinline__ unsigned int hash_cell(unsigned int c) {
    c *= 2654435761u;
    return (c >> 8) & HASH_MASK;
}

// ---------------------------------------------------------------------------
// 0) Clear hash + nnz (runs hidden under the memset on the other stream).
// ---------------------------------------------------------------------------
__global__ void clear_kernel() {
    unsigned int i = blockIdx.x * blockDim.x + threadIdx.x;
    if (i < HASH_SIZE) g_hash[i] = 0ull;
    if (i == 0) g_nnz = 0u;
}

// ---------------------------------------------------------------------------
// 1) Insert (cell, j). Duplicates: atomicMax keeps max j == last-write-wins
//    in (b,l) row-major order (XLA scatter semantics). First CAS into an
//    empty slot counts one unique cell -> sum(mask).
// ---------------------------------------------------------------------------
__global__ void insert_kernel(const int* __restrict__ idx_user,
                              const int* __restrict__ item_sets) {
    int j = blockIdx.x * blockDim.x + threadIdx.x;
    if (j >= NJ) return;
    int b = j / SETLEN;
    unsigned int u    = (unsigned int)__ldg(idx_user + b);
    unsigned int it   = (unsigned int)__ldg(item_sets + j);
    unsigned int cell = u * NUM_ITEM + it;

    unsigned long long keyhi = ((unsigned long long)(cell + 1u)) << 17;
    unsigned long long val   = keyhi | (unsigned long long)(unsigned int)j;

    unsigned int h = hash_cell(cell);
    while (true) {
        unsigned long long cur = g_hash[h];
        if (cur == 0ull) {
            unsigned long long old = atomicCAS(&g_hash[h], 0ull, val);
            if (old == 0ull) {                   // first occurrence of cell
                atomicAdd(&g_nnz, 1u);
                break;
            }
            cur = old;
        }
        if ((cur & ~IDX_MASK) == keyhi) {        // same key: keep max j
            atomicMax(&g_hash[h], val);
            break;
        }
        h = (h + 1u) & HASH_MASK;
    }
}

// ---------------------------------------------------------------------------
// 2) Winners compute their dot product and stash (cell, pred, label).
//    Every j writes g_cell[j] (0 for losers) -> deterministic per replay.
// ---------------------------------------------------------------------------
__global__ void prepare_kernel(const int*   __restrict__ idx_user,
                               const int*   __restrict__ item_sets,
                               const float* __restrict__ ratings,
                               const float* __restrict__ embed_user,
                               const float* __restrict__ embed_item) {
    int j = blockIdx.x * blockDim.x + threadIdx.x;
    if (j >= NJ) return;
    int b = j / SETLEN;
    unsigned int u    = (unsigned int)__ldg(idx_user + b);
    unsigned int it   = (unsigned int)__ldg(item_sets + j);
    unsigned int cell = u * NUM_ITEM + it;

    unsigned long long keyhi = ((unsigned long long)(cell + 1u)) << 17;
    unsigned int h = hash_cell(cell);
    unsigned long long cur;
    while (((cur = g_hash[h]) & ~IDX_MASK) != keyhi) h = (h + 1u) & HASH_MASK;

    if ((unsigned int)(cur & IDX_MASK) != (unsigned int)j) {
        g_cell[j] = 0u;                          // loser: clean slot
        return;
    }

    const float4* ur = (const float4*)(embed_user + (size_t)u  * NUM_HIDDEN);
    const float4* ir = (const float4*)(embed_item + (size_t)it * NUM_HIDDEN);
    float acc = 0.0f;
#pragma unroll
    for (int k = 0; k < NUM_HIDDEN / 4; k++) {
        float4 a = ur[k];
        float4 c = ir[k];
        acc = fmaf(a.x, c.x, acc);
        acc = fmaf(a.y, c.y, acc);
        acc = fmaf(a.z, c.z, acc);
        acc = fmaf(a.w, c.w, acc);
    }

    g_pred [j] = acc;
    g_label[j] = ratings[j];
    g_cell [j] = cell | WINNER_BIT;
}

// ---------------------------------------------------------------------------
// 3) Patch (after memset join): winners write two scattered floats.
// ---------------------------------------------------------------------------
__global__ void patch_kernel(float* __restrict__ out) {
    int j = blockIdx.x * blockDim.x + threadIdx.x;
    if (j == 0)
        out[2 * PLANE] = (float)((double)PLANE / (double)g_nnz);
    if (j >= NJ) return;

    unsigned int c = g_cell[j];
    if (c & WINNER_BIT) {
        unsigned int cell = c & ~WINNER_BIT;
        out[cell]         = g_pred[j];
        out[PLANE + cell] = g_label[j];
    }
}

// ---------------------------------------------------------------------------
// Fork-join: metadata pipeline on the main (captured) stream, 512MB memset
// on a non-blocking side stream, join before the patch. Streams/events are
// host objects created once (no device memory involved).
// ---------------------------------------------------------------------------
extern "C" void kernel_launch(void* const* d_in, const int* in_sizes, int n_in,
                              void* d_out, int out_size) {
    const int*   idx_user   = (const int*)  d_in[0];
    const int*   item_sets  = (const int*)  d_in[1];
    const float* rating     = (const float*)d_in[2];
    const float* embed_user = (const float*)d_in[3];
    const float* embed_item = (const float*)d_in[4];
    float* out = (float*)d_out;

    static cudaStream_t side = nullptr;
    static cudaEvent_t  ev_fork = nullptr, ev_done = nullptr;
    if (side == nullptr) {
        cudaStreamCreateWithFlags(&side, cudaStreamNonBlocking);
        cudaEventCreateWithFlags(&ev_fork, cudaEventDisableTiming);
        cudaEventCreateWithFlags(&ev_done, cudaEventDisableTiming);
    }

    // Fork: side stream zeroes both output planes (the ~80us HBM floor).
    cudaEventRecord(ev_fork, 0);
    cudaStreamWaitEvent(side, ev_fork, 0);
    cudaMemsetAsync(out, 0, 2ull * PLANE * sizeof(float), side);

    // Meanwhile on the main stream: clear hash, dedup, resolve winners.
    clear_kernel  <<<(HASH_SIZE + 255) / 256, 256>>>();
    insert_kernel <<<(NJ + 255) / 256, 256>>>(idx_user, item_sets);
    prepare_kernel<<<(NJ + 255) / 256, 256>>>(idx_user, item_sets, rating,
                                              embed_user, embed_item);

    // Join: patch must run after BOTH the memset and prepare.
    cudaEventRecord(ev_done, side);
    cudaStreamWaitEvent(0, ev_done, 0);
    patch_kernel<<<(NJ + 255) / 256, 256>>>(out);
}

// round 6
// speedup vs baseline: 2.2918x; 1.1057x over previous
#include <cuda_runtime.h>
#include <cstdint>

#define NUM_USER   4096
#define NUM_ITEM   16384
#define NUM_HIDDEN 64
#define BATCH      1024
#define SETLEN     50
#define NJ         (BATCH * SETLEN)              // 51200 scatter updates

#define PLANE      ((size_t)NUM_USER * NUM_ITEM) // 67,108,864 cells per plane

// The only persistent device state. INVARIANT: zero at the start of every
// launch / graph replay (pass2 thread 0 resets it after use).
__device__ unsigned int g_nnz;

// ---------------------------------------------------------------------------
// Pass 1: arbitrate duplicates IN the freshly-zeroed pred plane itself.
// Thread j tags its cell with j+1 via atomicMax -> surviving tag is the
// largest j == last-write-wins in (b,l) row-major order (XLA scatter
// semantics). The first thread to touch a cell (old==0) counts it for
// sum(mask). No hash table, no clear pass, no scratch arrays.
// ---------------------------------------------------------------------------
__global__ void tag_kernel(const int* __restrict__ idx_user,
                           const int* __restrict__ item_sets,
                           float* __restrict__ out) {
    int j = blockIdx.x * blockDim.x + threadIdx.x;
    if (j >= NJ) return;
    int b = j / SETLEN;
    unsigned int u    = (unsigned int)__ldg(idx_user + b);
    unsigned int it   = (unsigned int)__ldg(item_sets + j);
    unsigned int cell = u * NUM_ITEM + it;

    int old = atomicMax((int*)out + cell, j + 1);   // tags are 1..NJ, > 0
    if (old == 0) atomicAdd(&g_nnz, 1u);            // first toucher of cell
}

// ---------------------------------------------------------------------------
// Pass 2: the winner of each cell (tag == j+1) computes the 64-dim dot and
// overwrites the tag with the real prediction; label gets its rating.
// Every tagged cell has exactly one winner, so every tag is replaced by a
// real float and losers' cells are untouched here. Thread 0 writes the
// sparsity scalar and restores g_nnz = 0 (pristine state for next replay).
// ---------------------------------------------------------------------------
__global__ void resolve_kernel(const int*   __restrict__ idx_user,
                               const int*   __restrict__ item_sets,
                               const float* __restrict__ ratings,
                               const float* __restrict__ embed_user,
                               const float* __restrict__ embed_item,
                               float* __restrict__ out) {
    int j = blockIdx.x * blockDim.x + threadIdx.x;
    if (j == 0) {
        out[2 * PLANE] = (float)((double)PLANE / (double)g_nnz);
        g_nnz = 0u;                                 // self-cleaning invariant
    }
    if (j >= NJ) return;

    int b = j / SETLEN;
    unsigned int u    = (unsigned int)__ldg(idx_user + b);
    unsigned int it   = (unsigned int)__ldg(item_sets + j);
    unsigned int cell = u * NUM_ITEM + it;

    int tag = ((const int*)out)[cell];              // bit pattern from pass 1
    if (tag != j + 1) return;                       // not the winner

    // 64-dim dot product, float4-vectorized (rows are 256B-aligned; the
    // 5MB embedding tables are L2-resident after first touch).
    const float4* ur = (const float4*)(embed_user + (size_t)u  * NUM_HIDDEN);
    const float4* ir = (const float4*)(embed_item + (size_t)it * NUM_HIDDEN);
    float acc = 0.0f;
#pragma unroll
    for (int k = 0; k < NUM_HIDDEN / 4; k++) {
        float4 a = ur[k];
        float4 c = ir[k];
        acc = fmaf(a.x, c.x, acc);
        acc = fmaf(a.y, c.y, acc);
        acc = fmaf(a.z, c.z, acc);
        acc = fmaf(a.w, c.w, acc);
    }

    out[cell]         = acc;                        // pred_mask (replaces tag)
    out[PLANE + cell] = ratings[j];                 // label
}

// ---------------------------------------------------------------------------
// Serial 3-node pipeline: the 512MB zero-fill is the HBM floor (~80us);
// the two arbitration passes use the zeroed output itself as scratch.
// ---------------------------------------------------------------------------
extern "C" void kernel_launch(void* const* d_in, const int* in_sizes, int n_in,
                              void* d_out, int out_size) {
    const int*   idx_user   = (const int*)  d_in[0];
    const int*   item_sets  = (const int*)  d_in[1];
    const float* rating     = (const float*)d_in[2];
    const float* embed_user = (const float*)d_in[3];
    const float* embed_item = (const float*)d_in[4];
    float* out = (float*)d_out;

    cudaMemsetAsync(out, 0, 2ull * PLANE * sizeof(float), 0);
    tag_kernel    <<<(NJ + 255) / 256, 256>>>(idx_user, item_sets, out);
    resolve_kernel<<<(NJ + 255) / 256, 256>>>(idx_user, item_sets, rating,
                                              embed_user, embed_item, out);
}